// round 9
// baseline (speedup 1.0000x reference)
#include <cuda_runtime.h>
#include <cstdint>

#define BATCH 4
#define HW    16384
#define CDIM  256
#define HEADS 8

__device__ float g_G[BATCH * CDIM * CDIM];
__device__ float g_WeffT[BATCH * CDIM * CDIM];   // Weff^T : [n][k], k contiguous

__device__ __forceinline__ uint32_t f2tf(float x) {
    uint32_t r;
    asm("cvt.rna.tf32.f32 %0, %1;" : "=r"(r) : "f"(x));
    return r;
}

__device__ __forceinline__ void mma8(float* c, const uint32_t* a, const uint32_t* b) {
    asm volatile(
        "mma.sync.aligned.m16n8k8.row.col.f32.tf32.tf32.f32 "
        "{%0,%1,%2,%3}, {%4,%5,%6,%7}, {%8,%9}, {%0,%1,%2,%3};"
        : "+f"(c[0]), "+f"(c[1]), "+f"(c[2]), "+f"(c[3])
        : "r"(a[0]), "r"(a[1]), "r"(a[2]), "r"(a[3]), "r"(b[0]), "r"(b[1]));
}

__device__ __forceinline__ void cp16(uint32_t s, const float* g) {
    asm volatile("cp.async.cg.shared.global [%0], [%1], 16;" :: "r"(s), "l"(g));
}

// ---------------------------------------------------------------------------
// out = X @ Weff.  128 threads, CTA tile 128x128, warp tile 64x64 (2x2 warps).
// A = x[m][k], B = WeffT[n][k]; both k-contiguous in smem, row stride 40 words.
// k-permutation: thread t4 consumes logical k = {2t4, 2t4+1} -> LDS.64 pairs.
// B is pre-rounded to tf32 (weff_cvt) -> no cvt on B fragments.
// ---------------------------------------------------------------------------
__global__ __launch_bounds__(128, 2) void out_gemm(
    const float* __restrict__ xg, const float* __restrict__ wT,
    float* __restrict__ outg)
{
    extern __shared__ float smem[];
    float* As = smem;             // 2 stages x 128 rows x 40 words
    float* Bs = smem + 2 * 5120;  // 2 stages x 128 rows x 40 words

    const int tid  = threadIdx.x;
    const int lane = tid & 31;
    const int warp = tid >> 5;
    const int wm = warp >> 1, wn = warp & 1;
    const int g  = lane >> 2, t4 = lane & 3;
    const int b  = blockIdx.z;
    const int tm = blockIdx.x >> 1, tn = blockIdx.x & 1;

    const float* xb = xg + ((long)b * HW + (long)tm * 128) * CDIM;
    const float* wb = wT + (long)b * CDIM * CDIM + (long)tn * 128 * CDIM;

    const uint32_t sA = (uint32_t)__cvta_generic_to_shared(As);
    const uint32_t sB = (uint32_t)__cvta_generic_to_shared(Bs);

    const int row8 = tid >> 3, c16 = tid & 7;   // 128 rows handled 8 threads/row? no:
    // per-thread cp map: id = tid + r*128; row = id>>3 (0..127), c16 = id&7
    auto issue = [&](int buf, int k0) {
#pragma unroll
        for (int r = 0; r < 8; r++) {
            int id  = tid + r * 128;
            int row = id >> 3, c = id & 7;
            cp16(sA + (buf * 5120 + row * 40 + c * 4) * 4,
                 xb + (long)row * CDIM + k0 + c * 4);
        }
#pragma unroll
        for (int r = 0; r < 8; r++) {
            int id  = tid + r * 128;
            int row = id >> 3, c = id & 7;
            cp16(sB + (buf * 5120 + row * 40 + c * 4) * 4,
                 wb + (long)row * CDIM + k0 + c * 4);
        }
        asm volatile("cp.async.commit_group;");
    };
    (void)row8; (void)c16;

    float acc[4][8][4];
#pragma unroll
    for (int i = 0; i < 4; i++)
#pragma unroll
        for (int j = 0; j < 8; j++)
#pragma unroll
            for (int r = 0; r < 4; r++) acc[i][j][r] = 0.f;

    const int T = 8;   // K = 256 = 8 x 32
    issue(0, 0);
    for (int t = 0; t < T; t++) {
        if (t + 1 < T) {
            issue((t + 1) & 1, (t + 1) * 32);
            asm volatile("cp.async.wait_group 1;");
        } else {
            asm volatile("cp.async.wait_group 0;");
        }
        __syncthreads();
        const float* Ab = As + (t & 1) * 5120;
        const float* Bb = Bs + (t & 1) * 5120;
#pragma unroll
        for (int ks = 0; ks < 32; ks += 8) {
            uint32_t af[4][4];
#pragma unroll
            for (int mi = 0; mi < 4; mi++) {
                int r1 = wm * 64 + mi * 16 + g;
                uint2 p1 = *(const uint2*)&Ab[r1 * 40 + ks + 2 * t4];
                uint2 p2 = *(const uint2*)&Ab[(r1 + 8) * 40 + ks + 2 * t4];
                af[mi][0] = f2tf(__uint_as_float(p1.x));   // A[g][2t4]
                af[mi][2] = f2tf(__uint_as_float(p1.y));   // A[g][2t4+1]
                af[mi][1] = f2tf(__uint_as_float(p2.x));   // A[g+8][2t4]
                af[mi][3] = f2tf(__uint_as_float(p2.y));   // A[g+8][2t4+1]
            }
#pragma unroll
            for (int ni = 0; ni < 8; ni++) {
                int nr = wn * 64 + ni * 8 + g;
                uint2 bv = *(const uint2*)&Bb[nr * 40 + ks + 2 * t4];
                uint32_t bf[2] = { bv.x, bv.y };           // pre-rounded tf32
#pragma unroll
                for (int mi = 0; mi < 4; mi++)
                    mma8(acc[mi][ni], af[mi], bf);
            }
        }
        __syncthreads();
    }

    // epilogue: C row g -> cols (2t4, 2t4+1); rows g / g+8
    float* ob = outg + ((long)b * HW + (long)tm * 128) * CDIM + (long)tn * 128;
#pragma unroll
    for (int mi = 0; mi < 4; mi++) {
        int r1 = wm * 64 + mi * 16 + g;
#pragma unroll
        for (int ni = 0; ni < 8; ni++) {
            int cc = wn * 64 + ni * 8 + 2 * t4;
            *(float2*)&ob[(long)r1 * CDIM + cc]       = make_float2(acc[mi][ni][0], acc[mi][ni][1]);
            *(float2*)&ob[(long)(r1 + 8) * CDIM + cc] = make_float2(acc[mi][ni][2], acc[mi][ni][3]);
        }
    }
}

// ---------------------------------------------------------------------------
// Gram: G[b] = X_b^T X_b. 128 threads, CTA tile 128x128, warp tile 64x64.
// A,B are k-major [k][m] slices of x (stride 136); symmetric 3-tile + mirror;
// diagonal tiles alias B to A (skip B loads). Split-K 64 + atomic epilogue.
// ---------------------------------------------------------------------------
__global__ __launch_bounds__(128, 2) void gram_gemm(
    const float* __restrict__ xg, float* __restrict__ Gg)
{
    extern __shared__ float smem[];
    float* As = smem;             // 3 stages x 32 x 136
    float* Bs = smem + 3 * 4352;

    const int tid  = threadIdx.x;
    const int lane = tid & 31;
    const int warp = tid >> 5;
    const int wm = warp >> 1, wn = warp & 1;
    const int g  = lane >> 2, t4 = lane & 3;
    const int b  = blockIdx.z;

    const int tileId = blockIdx.x % 3;
    const int split  = blockIdx.x / 3;           // 0..63
    const int tm = (tileId == 2) ? 1 : 0;
    const int tn = (tileId == 0) ? 0 : 1;
    const bool same = (tm == tn);

    const float* xb = xg + (long)b * HW * CDIM;
    float* Gp = Gg + (long)b * CDIM * CDIM;
    const int k0base = split * 256;              // 8 chunks of 32

    const uint32_t sA = (uint32_t)__cvta_generic_to_shared(As);
    const uint32_t sB = (uint32_t)__cvta_generic_to_shared(Bs);

    auto issue = [&](int buf, int k0) {
#pragma unroll
        for (int r = 0; r < 8; r++) {
            int id = tid + r * 128;
            int k = id >> 5, m4 = (id & 31) << 2;
            cp16(sA + (buf * 4352 + k * 136 + m4) * 4,
                 xb + (long)(k0 + k) * CDIM + tm * 128 + m4);
        }
        if (!same) {
#pragma unroll
            for (int r = 0; r < 8; r++) {
                int id = tid + r * 128;
                int k = id >> 5, m4 = (id & 31) << 2;
                cp16(sB + (buf * 4352 + k * 136 + m4) * 4,
                     xb + (long)(k0 + k) * CDIM + tn * 128 + m4);
            }
        }
        asm volatile("cp.async.commit_group;");
    };

    float acc[4][8][4];
#pragma unroll
    for (int i = 0; i < 4; i++)
#pragma unroll
        for (int j = 0; j < 8; j++)
#pragma unroll
            for (int r = 0; r < 4; r++) acc[i][j][r] = 0.f;

    const int T = 8;
    issue(0, k0base);
    issue(1, k0base + 32);
    int buf = 0;
    for (int t = 0; t < T; t++) {
        if (t + 2 < T) {
            issue((buf + 2) % 3, k0base + (t + 2) * 32);
            asm volatile("cp.async.wait_group 2;");
        } else if (t + 1 < T) {
            asm volatile("cp.async.wait_group 1;");
        } else {
            asm volatile("cp.async.wait_group 0;");
        }
        __syncthreads();
        const float* Ab = As + buf * 4352;
        const float* Bb = same ? Ab : (Bs + buf * 4352);
#pragma unroll
        for (int ks = 0; ks < 32; ks += 8) {
            uint32_t af[4][4];
#pragma unroll
            for (int mi = 0; mi < 4; mi++) {
                int m0 = wm * 64 + mi * 16 + g;
                af[mi][0] = f2tf(Ab[(ks + t4) * 136 + m0]);
                af[mi][1] = f2tf(Ab[(ks + t4) * 136 + m0 + 8]);
                af[mi][2] = f2tf(Ab[(ks + t4 + 4) * 136 + m0]);
                af[mi][3] = f2tf(Ab[(ks + t4 + 4) * 136 + m0 + 8]);
            }
#pragma unroll
            for (int ni = 0; ni < 8; ni++) {
                int n0 = wn * 64 + ni * 8 + g;
                uint32_t bf[2];
                bf[0] = f2tf(Bb[(ks + t4) * 136 + n0]);
                bf[1] = f2tf(Bb[(ks + t4 + 4) * 136 + n0]);
#pragma unroll
                for (int mi = 0; mi < 4; mi++)
                    mma8(acc[mi][ni], af[mi], bf);
            }
        }
        __syncthreads();
        buf = (buf + 1) % 3;
    }

    const bool mirror = (tm != tn);
#pragma unroll
    for (int mi = 0; mi < 4; mi++) {
        int row = tm * 128 + wm * 64 + mi * 16 + g;
#pragma unroll
        for (int ni = 0; ni < 8; ni++) {
            int col = tn * 128 + wn * 64 + ni * 8 + 2 * t4;
            atomicAdd(&Gp[(long)row * CDIM + col],           acc[mi][ni][0]);
            atomicAdd(&Gp[(long)row * CDIM + col + 1],       acc[mi][ni][1]);
            atomicAdd(&Gp[(long)(row + 8) * CDIM + col],     acc[mi][ni][2]);
            atomicAdd(&Gp[(long)(row + 8) * CDIM + col + 1], acc[mi][ni][3]);
            if (mirror) {
                atomicAdd(&Gp[(long)col * CDIM + row],           acc[mi][ni][0]);
                atomicAdd(&Gp[(long)(col + 1) * CDIM + row],     acc[mi][ni][1]);
                atomicAdd(&Gp[(long)col * CDIM + row + 8],       acc[mi][ni][2]);
                atomicAdd(&Gp[(long)(col + 1) * CDIM + row + 8], acc[mi][ni][3]);
            }
        }
    }
}

// In-place RNA-round WeffT to tf32 (idempotent; lets out_gemm skip B cvts).
__global__ void weff_cvt_kernel(float* w) {
    int i = blockIdx.x * blockDim.x + threadIdx.x;
    float4 v = ((float4*)w)[i];
    uint4 u;
    u.x = f2tf(v.x); u.y = f2tf(v.y); u.z = f2tf(v.z); u.w = f2tf(v.w);
    ((uint4*)w)[i] = u;
}

// ---------------------------------------------------------------------------
// Fused middle: one CTA per (head, batch). Emits Weff TRANSPOSED ([n][k]).
// ---------------------------------------------------------------------------
__global__ __launch_bounds__(256) void fused_middle(
    const float* __restrict__ Gg, const float* __restrict__ Wq,
    const float* __restrict__ Wk, const float* __restrict__ Wv,
    const float* __restrict__ Wout, float* __restrict__ WeffT)
{
    extern __shared__ uint32_t smw[];
    uint32_t* SW  = smw;
    uint32_t* SG  = smw + 18432;
    uint32_t* SQK = smw + 35072;
    float* SMM  = (float*)(smw + 53504);
    float* SATT = (float*)(smw + 54560);
    float* SDQ  = (float*)(smw + 55616);
    float* SDK  = (float*)(smw + 55648);

    const int h = blockIdx.x;
    const int b = blockIdx.z;
    const float* G = Gg + (long)b * CDIM * CDIM;
    float* Wf = WeffT + (long)b * CDIM * CDIM;

    const int tid  = threadIdx.x;
    const int lane = tid & 31;
    const int warp = tid >> 5;
    const int g  = lane >> 2;
    const int t4 = lane & 3;

    for (int i = tid; i < 256 * 64; i += 256) {
        int k = i >> 6, n = i & 63;
        float v = (n < 32) ? Wq[k * CDIM + h * 32 + n]
                           : Wk[k * CDIM + h * 32 + (n - 32)];
        SW[k * 72 + n] = f2tf(v);
    }
    __syncthreads();

    const int m0 = (warp & 3) * 16;
    const int n0 = (warp >> 2) * 32;
    for (int mb = 0; mb < 4; mb++) {
        for (int i = tid; i < 4096; i += 256) {
            int row = i >> 6, c4 = (i & 63) << 2;
            float4 v = *(const float4*)(G + (long)(mb * 64 + row) * 256 + c4);
            uint32_t* d = SG + row * 260 + c4;
            d[0] = f2tf(v.x); d[1] = f2tf(v.y); d[2] = f2tf(v.z); d[3] = f2tf(v.w);
        }
        __syncthreads();
        float acc[4][4];
#pragma unroll
        for (int i = 0; i < 4; i++)
#pragma unroll
            for (int r = 0; r < 4; r++) acc[i][r] = 0.f;
#pragma unroll 8
        for (int ks = 0; ks < 256; ks += 8) {
            uint32_t af[4], bf[4][2];
            af[0] = SG[(m0 + g) * 260 + ks + t4];
            af[1] = SG[(m0 + g + 8) * 260 + ks + t4];
            af[2] = SG[(m0 + g) * 260 + ks + t4 + 4];
            af[3] = SG[(m0 + g + 8) * 260 + ks + t4 + 4];
#pragma unroll
            for (int nf = 0; nf < 4; nf++) {
                int nn = n0 + nf * 8;
                bf[nf][0] = SW[(ks + t4) * 72 + nn + g];
                bf[nf][1] = SW[(ks + t4 + 4) * 72 + nn + g];
            }
#pragma unroll
            for (int nf = 0; nf < 4; nf++) mma8(acc[nf], af, bf[nf]);
        }
#pragma unroll
        for (int nf = 0; nf < 4; nf++) {
            int nn = n0 + nf * 8 + t4 * 2;
            int rr = mb * 64 + m0 + g;
            SQK[rr * 72 + nn]       = __float_as_uint(acc[nf][0]);
            SQK[rr * 72 + nn + 1]   = __float_as_uint(acc[nf][1]);
            SQK[(rr + 8) * 72 + nn]     = __float_as_uint(acc[nf][2]);
            SQK[(rr + 8) * 72 + nn + 1] = __float_as_uint(acc[nf][3]);
        }
        __syncthreads();
    }

    {
        int e = tid & 31, cb = warp * 4;
        float a0 = 0.f, a1 = 0.f, a2 = 0.f, a3 = 0.f;
        for (int m = 0; m < 256; m++) {
            float kv = __uint_as_float(SQK[m * 72 + 32 + e]);
            a0 += __uint_as_float(SW[m * 72 + cb + 0]) * kv;
            a1 += __uint_as_float(SW[m * 72 + cb + 1]) * kv;
            a2 += __uint_as_float(SW[m * 72 + cb + 2]) * kv;
            a3 += __uint_as_float(SW[m * 72 + cb + 3]) * kv;
        }
        SMM[(cb + 0) * 33 + e] = a0;
        SMM[(cb + 1) * 33 + e] = a1;
        SMM[(cb + 2) * 33 + e] = a2;
        SMM[(cb + 3) * 33 + e] = a3;
        if (tid < 32) {
            float d = 0.f;
            for (int m = 0; m < 256; m++)
                d += __uint_as_float(SW[m * 72 + tid]) * __uint_as_float(SQK[m * 72 + tid]);
            SDQ[tid] = d;
        } else if (tid < 64) {
            int e2 = tid - 32;
            float d = 0.f;
            for (int m = 0; m < 256; m++)
                d += __uint_as_float(SW[m * 72 + 32 + e2]) * __uint_as_float(SQK[m * 72 + 32 + e2]);
            SDK[e2] = d;
        }
    }
    __syncthreads();

    {
        float nk = rsqrtf(SDK[lane]);
#pragma unroll
        for (int r = 0; r < 4; r++) {
            int c = warp * 4 + r;
            float nq = rsqrtf(SDQ[c]);
            float l = SMM[c * 33 + lane] * nq * nk * (1.0f / 128.0f);
            float mx = l;
            for (int o = 16; o; o >>= 1) mx = fmaxf(mx, __shfl_xor_sync(0xffffffffu, mx, o));
            float p = __expf(l - mx);
            float s = p;
            for (int o = 16; o; o >>= 1) s += __shfl_xor_sync(0xffffffffu, s, o);
            SATT[c * 33 + lane] = p / s;
        }
    }
    __syncthreads();

    uint32_t* SWv = smw;
    uint32_t* SWx = smw + 9216;
    {
        float wo[32];
#pragma unroll
        for (int c = 0; c < 32; c++) wo[c] = Wout[(h * 32 + c) * CDIM + tid];
        for (int e = 0; e < 32; e++) {
            float a = 0.f;
#pragma unroll
            for (int c = 0; c < 32; c++) a += SATT[c * 33 + e] * wo[c];
            SWx[e * 264 + tid] = f2tf(a);
        }
        for (int i = tid; i < 8192; i += 256) {
            int m = i >> 5, e = i & 31;
            SWv[m * 36 + e] = f2tf(Wv[m * CDIM + h * 32 + e]);
        }
    }
    __syncthreads();

    {
        const int m0w = warp * 32;
        for (int nc = 0; nc < 4; nc++) {
            float acc[2][8][4];
#pragma unroll
            for (int mi = 0; mi < 2; mi++)
#pragma unroll
                for (int nf = 0; nf < 8; nf++)
#pragma unroll
                    for (int r = 0; r < 4; r++) acc[mi][nf][r] = 0.f;
#pragma unroll
            for (int ks = 0; ks < 32; ks += 8) {
                uint32_t af[2][4];
#pragma unroll
                for (int mi = 0; mi < 2; mi++) {
                    int mm = m0w + mi * 16;
                    af[mi][0] = SWv[(mm + g) * 36 + ks + t4];
                    af[mi][1] = SWv[(mm + g + 8) * 36 + ks + t4];
                    af[mi][2] = SWv[(mm + g) * 36 + ks + t4 + 4];
                    af[mi][3] = SWv[(mm + g + 8) * 36 + ks + t4 + 4];
                }
#pragma unroll
                for (int nf = 0; nf < 8; nf++) {
                    int nn = nc * 64 + nf * 8 + g;
                    uint32_t bf[2];
                    bf[0] = SWx[(ks + t4) * 264 + nn];
                    bf[1] = SWx[(ks + t4 + 4) * 264 + nn];
                    mma8(acc[0][nf], af[0], bf);
                    mma8(acc[1][nf], af[1], bf);
                }
            }
            // transposed accumulate: WeffT[n][k] += v  (k = Wv row index)
#pragma unroll
            for (int mi = 0; mi < 2; mi++) {
#pragma unroll
                for (int nf = 0; nf < 8; nf++) {
                    int rr = m0w + mi * 16 + g;
                    int cc = nc * 64 + nf * 8 + t4 * 2;
                    atomicAdd(&Wf[cc * 256 + rr],           acc[mi][nf][0]);
                    atomicAdd(&Wf[(cc + 1) * 256 + rr],     acc[mi][nf][1]);
                    atomicAdd(&Wf[cc * 256 + rr + 8],       acc[mi][nf][2]);
                    atomicAdd(&Wf[(cc + 1) * 256 + rr + 8], acc[mi][nf][3]);
                }
            }
        }
    }
}

// ---------------------------------------------------------------------------
extern "C" void kernel_launch(void* const* d_in, const int* in_sizes, int n_in,
                              void* d_out, int out_size) {
    (void)in_sizes; (void)n_in; (void)out_size;
    const float* x    = (const float*)d_in[0];
    const float* Wq   = (const float*)d_in[1];
    const float* Wk   = (const float*)d_in[2];
    const float* Wv   = (const float*)d_in[3];
    const float* Wout = (const float*)d_in[4];
    float* out = (float*)d_out;

    float *G, *WeffT;
    cudaGetSymbolAddress((void**)&G,     g_G);
    cudaGetSymbolAddress((void**)&WeffT, g_WeffT);

    const int smemGram  = 6 * 4352 * 4;     // 104448 (3 stages x (A+B))
    const int smemOut   = 4 * 5120 * 4;     // 81920  (2 stages x (A+B))
    const int smemFused = 55680 * 4;        // 222720

    cudaFuncSetAttribute(gram_gemm,
                         cudaFuncAttributeMaxDynamicSharedMemorySize, smemGram);
    cudaFuncSetAttribute(out_gemm,
                         cudaFuncAttributeMaxDynamicSharedMemorySize, smemOut);
    cudaFuncSetAttribute(fused_middle,
                         cudaFuncAttributeMaxDynamicSharedMemorySize, smemFused);

    cudaMemsetAsync(G,     0, BATCH * CDIM * CDIM * sizeof(float));
    cudaMemsetAsync(WeffT, 0, BATCH * CDIM * CDIM * sizeof(float));

    // G[b] = X_b^T X_b : 3 symmetric tiles x 64 k-splits
    {
        dim3 gr(3 * 64, 1, BATCH);
        gram_gemm<<<gr, 128, smemGram>>>(x, G);
    }

    // fused middle -> WeffT
    {
        dim3 gr(HEADS, 1, BATCH);
        fused_middle<<<gr, 256, smemFused>>>(G, Wq, Wk, Wv, Wout, WeffT);
    }

    // pre-round WeffT to tf32 once
    weff_cvt_kernel<<<(BATCH * CDIM * CDIM / 4) / 256, 256>>>(WeffT);

    // out = X @ Weff
    {
        dim3 gr(128 * 2, 1, BATCH);
        out_gemm<<<gr, 128, smemOut>>>(x, WeffT, out);
    }
}